// round 4
// baseline (speedup 1.0000x reference)
#include <cuda_runtime.h>
#include <cuda_fp16.h>
#include <cstdint>

// Problem constants
#define IM_PIX   16384      // 128*128 pixels
#define BC       32         // 2*16 maps
#define HT_BINS  33120      // 184*180
#define N_VOTES  4000000
#define INV_NORM (1.0f/128.0f)
#define CAP      256        // per-bin bucket capacity (Poisson mean 121, 12-sigma safe)

// Scratch (__device__ globals; allocation-free rule)
__device__ __half g_xTh[IM_PIX * BC];          // pixel-major fp16 gather table, 1 MB
__device__ float  g_acc[HT_BINS * BC];         // overflow-fallback accumulator, 4.24 MB
__device__ int    g_cnt[HT_BINS];              // per-bin vote counts
__device__ uint2  g_bucket[(size_t)HT_BINS * CAP];  // {pixel, weight_bits}, 67.8 MB

// ---------------------------------------------------------------------------
// Zero counters + fallback accumulator
// ---------------------------------------------------------------------------
__global__ void zero_kernel() {
    int i = blockIdx.x * blockDim.x + threadIdx.x;
    if (i < (HT_BINS * BC) / 4)
        reinterpret_cast<float4*>(g_acc)[i] = make_float4(0.f, 0.f, 0.f, 0.f);
    if (i < HT_BINS)
        g_cnt[i] = 0;
}

// ---------------------------------------------------------------------------
// Transpose x [BC, IM_PIX] fp32 -> g_xTh [IM_PIX, BC] fp16, tiled via smem
// ---------------------------------------------------------------------------
__global__ void transpose_x_kernel(const float* __restrict__ x) {
    __shared__ float tile[32][64 + 1];
    int p0 = blockIdx.x * 64;
    int t  = threadIdx.x;
    #pragma unroll
    for (int i = 0; i < 8; i++) {
        int idx = t + i * 256;          // idx = m*64 + pl
        int m  = idx >> 6;
        int pl = idx & 63;
        tile[m][pl] = x[(size_t)m * IM_PIX + p0 + pl];
    }
    __syncthreads();
    #pragma unroll
    for (int i = 0; i < 8; i++) {
        int idx = t + i * 256;          // idx = pl*32 + m
        int pl = idx >> 5;
        int m  = idx & 31;
        g_xTh[(size_t)(p0 + pl) * BC + m] = __float2half(tile[m][pl]);
    }
}

// ---------------------------------------------------------------------------
// Scatter votes into per-bin buckets. One thread per vote.
// 4M spread-address counter atomics (cheap) + one 8B payload write.
// Overflow (never in practice): correct fallback via global fp32 atomics.
// ---------------------------------------------------------------------------
__global__ void scatter_kernel(const int*   __restrict__ vp,
                               const int*   __restrict__ vb,
                               const float* __restrict__ vw) {
    int v = blockIdx.x * blockDim.x + threadIdx.x;
    if (v >= N_VOTES) return;
    int   p = vp[v];
    int   b = vb[v];
    float w = vw[v];
    int pos = atomicAdd(&g_cnt[b], 1);
    if (pos < CAP) {
        g_bucket[(size_t)b * CAP + pos] = make_uint2((unsigned)p, __float_as_uint(w));
    } else {
        float*        dst = g_acc + (size_t)b * BC;
        const __half* src = g_xTh + (size_t)p * BC;
        #pragma unroll
        for (int m = 0; m < BC; m++)
            atomicAdd(dst + m, __half2float(src[m]) * w);
    }
}

// ---------------------------------------------------------------------------
// Accumulate: one warp per bin, zero atomics.
//   half = lane>>4 selects one of 2 votes processed per step;
//   sub  = lane&15 selects the map pair (2*sub, 2*sub+1) -> one LDG.U32
//   serves 2 fp16 map values, so one warp-LDG covers 2 votes x 32 maps.
// Final: halves combined via shfl_xor(16); lanes 0-15 write out directly.
// ---------------------------------------------------------------------------
__global__ void accum_kernel(float* __restrict__ out) {
    int warp = (blockIdx.x * blockDim.x + threadIdx.x) >> 5;
    int lane = threadIdx.x & 31;
    if (warp >= HT_BINS) return;
    int b    = warp;
    int half = lane >> 4;
    int sub  = lane & 15;

    int n = g_cnt[b];
    if (n > CAP) n = CAP;

    float2 acc = make_float2(0.f, 0.f);
    if (half == 0) {   // fold in the (normally zero) overflow accumulator once
        acc = *(reinterpret_cast<const float2*>(g_acc + (size_t)b * BC) + sub);
    }

    const uint2* bucket = g_bucket + (size_t)b * CAP;
    for (int base = 0; base < n; base += 32) {
        int   idx = base + lane;
        uint2 pk  = (idx < n) ? bucket[idx] : make_uint2(0u, 0u);  // w=0 pad
        #pragma unroll
        for (int s = 0; s < 32; s += 2) {
            if (base + s >= n) break;                  // warp-uniform
            int src  = s + half;                       // my half-warp's vote slot
            unsigned pu = __shfl_sync(0xffffffffu, pk.x, src);
            unsigned wu = __shfl_sync(0xffffffffu, pk.y, src);
            float w = __uint_as_float(wu);
            __half2 h = *(reinterpret_cast<const __half2*>(g_xTh + (size_t)pu * BC) + sub);
            float2  f = __half22float2(h);
            acc.x += f.x * w;
            acc.y += f.y * w;
        }
    }

    // combine the two half-warps' partial sums
    acc.x += __shfl_xor_sync(0xffffffffu, acc.x, 16);
    acc.y += __shfl_xor_sync(0xffffffffu, acc.y, 16);

    if (half == 0) {
        out[(size_t)(2 * sub)     * HT_BINS + b] = acc.x * INV_NORM;
        out[(size_t)(2 * sub + 1) * HT_BINS + b] = acc.y * INV_NORM;
    }
}

// ---------------------------------------------------------------------------
// Launch pipeline (all async, graph-capturable)
// ---------------------------------------------------------------------------
extern "C" void kernel_launch(void* const* d_in, const int* in_sizes, int n_in,
                              void* d_out, int out_size) {
    const float* x  = (const float*)d_in[0];   // [2,16,128,128] fp32
    const int*   vp = (const int*)  d_in[1];   // vote_pixel  [4M]
    const int*   vb = (const int*)  d_in[2];   // vote_bin    [4M]
    const float* vw = (const float*)d_in[3];   // vote_weight [4M]
    float* out = (float*)d_out;                // [2,16,184,180] fp32

    const int TB = 256;

    zero_kernel       <<<((HT_BINS * BC / 4) + TB - 1) / TB, TB>>>();
    transpose_x_kernel<<<IM_PIX / 64, TB>>>(x);
    scatter_kernel    <<<(N_VOTES + TB - 1) / TB, TB>>>(vp, vb, vw);

    int warps_needed = HT_BINS;
    int blocks = (warps_needed * 32 + TB - 1) / TB;
    accum_kernel<<<blocks, TB>>>(out);
}

// round 5
// speedup vs baseline: 1.0188x; 1.0188x over previous
#include <cuda_runtime.h>
#include <cuda_fp16.h>
#include <cstdint>

// Problem constants
#define IM_PIX   16384      // 128*128 pixels
#define BC       32         // 2*16 maps
#define HT_BINS  33120      // 184*180
#define N_VOTES  4000000
#define INV_NORM (1.0f/128.0f)
#define CAP      256        // per-bin bucket capacity (Poisson mean 121, 12-sigma safe)

// Scratch (__device__ globals; allocation-free rule)
__device__ __half g_xTh[IM_PIX * BC];          // pixel-major fp16 gather table, 1 MB
__device__ float  g_acc[HT_BINS * BC];         // overflow-fallback accumulator, 4.24 MB
__device__ int    g_cnt[HT_BINS];              // per-bin vote counts
__device__ uint2  g_bucket[(size_t)HT_BINS * CAP];  // {pixel, weight_bits}, 67.8 MB

// ---------------------------------------------------------------------------
// Zero counters + fallback accumulator
// ---------------------------------------------------------------------------
__global__ void zero_kernel() {
    int i = blockIdx.x * blockDim.x + threadIdx.x;
    if (i < (HT_BINS * BC) / 4)
        reinterpret_cast<float4*>(g_acc)[i] = make_float4(0.f, 0.f, 0.f, 0.f);
    if (i < HT_BINS)
        g_cnt[i] = 0;
}

// ---------------------------------------------------------------------------
// Transpose x [BC, IM_PIX] fp32 -> g_xTh [IM_PIX, BC] fp16, tiled via smem
// ---------------------------------------------------------------------------
__global__ void transpose_x_kernel(const float* __restrict__ x) {
    __shared__ float tile[32][64 + 1];
    int p0 = blockIdx.x * 64;
    int t  = threadIdx.x;
    #pragma unroll
    for (int i = 0; i < 8; i++) {
        int idx = t + i * 256;          // idx = m*64 + pl
        int m  = idx >> 6;
        int pl = idx & 63;
        tile[m][pl] = x[(size_t)m * IM_PIX + p0 + pl];
    }
    __syncthreads();
    #pragma unroll
    for (int i = 0; i < 8; i++) {
        int idx = t + i * 256;          // idx = pl*32 + m
        int pl = idx >> 5;
        int m  = idx & 31;
        g_xTh[(size_t)(p0 + pl) * BC + m] = __float2half(tile[m][pl]);
    }
}

// ---------------------------------------------------------------------------
// Scatter votes into per-bin buckets. One thread per vote.
// 4M spread-address counter atomics (cheap) + one 8B payload write.
// Overflow (never in practice): correct fallback via global fp32 atomics.
// ---------------------------------------------------------------------------
__global__ void scatter_kernel(const int*   __restrict__ vp,
                               const int*   __restrict__ vb,
                               const float* __restrict__ vw) {
    int v = blockIdx.x * blockDim.x + threadIdx.x;
    if (v >= N_VOTES) return;
    int   p = vp[v];
    int   b = vb[v];
    float w = vw[v];
    int pos = atomicAdd(&g_cnt[b], 1);
    if (pos < CAP) {
        g_bucket[(size_t)b * CAP + pos] = make_uint2((unsigned)p, __float_as_uint(w));
    } else {
        float*        dst = g_acc + (size_t)b * BC;
        const __half* src = g_xTh + (size_t)p * BC;
        #pragma unroll
        for (int m = 0; m < BC; m++)
            atomicAdd(dst + m, __half2float(src[m]) * w);
    }
}

// ---------------------------------------------------------------------------
// Accumulate: one warp per bin, zero atomics.
//   half = lane>>4 selects one of 2 votes processed per step;
//   sub  = lane&15 selects the map pair (2*sub, 2*sub+1) -> one LDG.U32
//   serves 2 fp16 map values, so one warp-LDG covers 2 votes x 32 maps.
// Final: halves combined via shfl_xor(16); lanes 0-15 write out directly.
// ---------------------------------------------------------------------------
__global__ void accum_kernel(float* __restrict__ out) {
    int warp = (blockIdx.x * blockDim.x + threadIdx.x) >> 5;
    int lane = threadIdx.x & 31;
    if (warp >= HT_BINS) return;
    int b    = warp;
    int half = lane >> 4;
    int sub  = lane & 15;

    int n = g_cnt[b];
    if (n > CAP) n = CAP;

    float2 acc = make_float2(0.f, 0.f);
    if (half == 0) {   // fold in the (normally zero) overflow accumulator once
        acc = *(reinterpret_cast<const float2*>(g_acc + (size_t)b * BC) + sub);
    }

    const uint2* bucket = g_bucket + (size_t)b * CAP;
    for (int base = 0; base < n; base += 32) {
        int   idx = base + lane;
        uint2 pk  = (idx < n) ? bucket[idx] : make_uint2(0u, 0u);  // w=0 pad
        #pragma unroll
        for (int s = 0; s < 32; s += 2) {
            if (base + s >= n) break;                  // warp-uniform
            int src  = s + half;                       // my half-warp's vote slot
            unsigned pu = __shfl_sync(0xffffffffu, pk.x, src);
            unsigned wu = __shfl_sync(0xffffffffu, pk.y, src);
            float w = __uint_as_float(wu);
            __half2 h = *(reinterpret_cast<const __half2*>(g_xTh + (size_t)pu * BC) + sub);
            float2  f = __half22float2(h);
            acc.x += f.x * w;
            acc.y += f.y * w;
        }
    }

    // combine the two half-warps' partial sums
    acc.x += __shfl_xor_sync(0xffffffffu, acc.x, 16);
    acc.y += __shfl_xor_sync(0xffffffffu, acc.y, 16);

    if (half == 0) {
        out[(size_t)(2 * sub)     * HT_BINS + b] = acc.x * INV_NORM;
        out[(size_t)(2 * sub + 1) * HT_BINS + b] = acc.y * INV_NORM;
    }
}

// ---------------------------------------------------------------------------
// Launch pipeline (all async, graph-capturable)
// ---------------------------------------------------------------------------
extern "C" void kernel_launch(void* const* d_in, const int* in_sizes, int n_in,
                              void* d_out, int out_size) {
    const float* x  = (const float*)d_in[0];   // [2,16,128,128] fp32
    const int*   vp = (const int*)  d_in[1];   // vote_pixel  [4M]
    const int*   vb = (const int*)  d_in[2];   // vote_bin    [4M]
    const float* vw = (const float*)d_in[3];   // vote_weight [4M]
    float* out = (float*)d_out;                // [2,16,184,180] fp32

    const int TB = 256;

    zero_kernel       <<<((HT_BINS * BC / 4) + TB - 1) / TB, TB>>>();
    transpose_x_kernel<<<IM_PIX / 64, TB>>>(x);
    scatter_kernel    <<<(N_VOTES + TB - 1) / TB, TB>>>(vp, vb, vw);

    int warps_needed = HT_BINS;
    int blocks = (warps_needed * 32 + TB - 1) / TB;
    accum_kernel<<<blocks, TB>>>(out);
}

// round 6
// speedup vs baseline: 1.3211x; 1.2967x over previous
#include <cuda_runtime.h>
#include <cuda_fp16.h>
#include <cstdint>

// Problem constants
#define IM_PIX   16384      // 128*128 pixels
#define BC       32         // 2*16 maps
#define HT_BINS  33120      // 184*180
#define N_VOTES  4000000
#define INV_NORM (1.0f/128.0f)
#define CAP      192        // per-bin capacity; Poisson(121), 6.4 sigma, with correct fallback

// Scratch (__device__ globals; allocation-free rule)
__device__ __half   g_xTh[IM_PIX * BC];              // pixel-major fp16 table, 1 MB
__device__ float    g_acc[HT_BINS * BC];             // accumulator (overflow + warp partials)
__device__ int      g_cnt[HT_BINS];                  // per-bin vote counts
__device__ unsigned g_bucket[(size_t)HT_BINS * CAP]; // packed votes p<<16|fp16(w), 25.4 MB (L2-resident)

// ---------------------------------------------------------------------------
// Zero counters + accumulator
// ---------------------------------------------------------------------------
__global__ void zero_kernel() {
    int i = blockIdx.x * blockDim.x + threadIdx.x;
    if (i < (HT_BINS * BC) / 4)
        reinterpret_cast<float4*>(g_acc)[i] = make_float4(0.f, 0.f, 0.f, 0.f);
    if (i < HT_BINS)
        g_cnt[i] = 0;
}

// ---------------------------------------------------------------------------
// Transpose x [BC, IM_PIX] fp32 -> g_xTh [IM_PIX, BC] fp16, tiled via smem
// ---------------------------------------------------------------------------
__global__ void transpose_x_kernel(const float* __restrict__ x) {
    __shared__ float tile[32][64 + 1];
    int p0 = blockIdx.x * 64;
    int t  = threadIdx.x;
    #pragma unroll
    for (int i = 0; i < 8; i++) {
        int idx = t + i * 256;          // idx = m*64 + pl
        int m  = idx >> 6;
        int pl = idx & 63;
        tile[m][pl] = x[(size_t)m * IM_PIX + p0 + pl];
    }
    __syncthreads();
    #pragma unroll
    for (int i = 0; i < 8; i++) {
        int idx = t + i * 256;          // idx = pl*32 + m
        int pl = idx >> 5;
        int m  = idx & 31;
        g_xTh[(size_t)(p0 + pl) * BC + m] = __float2half(tile[m][pl]);
    }
}

// ---------------------------------------------------------------------------
// Scatter votes into per-bin buckets, 4B packed entries.
// Overflow fallback (probability ~0) reads the ORIGINAL x: exact and
// independent of the transpose kernel.
// ---------------------------------------------------------------------------
__global__ void scatter_kernel(const float* __restrict__ x,
                               const int*   __restrict__ vp,
                               const int*   __restrict__ vb,
                               const float* __restrict__ vw) {
    int v = blockIdx.x * blockDim.x + threadIdx.x;
    if (v >= N_VOTES) return;
    int   p = vp[v];
    int   b = vb[v];
    float w = vw[v];
    int pos = atomicAdd(&g_cnt[b], 1);
    if (pos < CAP) {
        unsigned packed = ((unsigned)p << 16)
                        | (unsigned)__half_as_ushort(__float2half(w));
        g_bucket[(size_t)b * CAP + pos] = packed;
    } else {
        float* dst = g_acc + (size_t)b * BC;
        #pragma unroll
        for (int m = 0; m < BC; m++)
            atomicAdd(dst + m, x[(size_t)m * IM_PIX + p] * w);
    }
}

// ---------------------------------------------------------------------------
// Accumulate: 2 warps per bin (part = warp&1 takes interleaved 32-chunks).
// Lane = (half, sub): half-warps process 2 votes per step, sub = map pair.
// Pads are packed=0 -> w=+0.0 -> harmless FMA, so no per-step branch.
// Warp partials -> red.global.add.v2.f32 into g_acc (1M lane-ops, ~3us).
// ---------------------------------------------------------------------------
__global__ void accum_kernel() {
    int gw = (blockIdx.x * blockDim.x + threadIdx.x) >> 5;
    if (gw >= HT_BINS * 2) return;
    int b    = gw >> 1;
    int part = gw & 1;
    int lane = threadIdx.x & 31;
    int half = lane >> 4;
    int sub  = lane & 15;

    int n = g_cnt[b];
    if (n > CAP) n = CAP;

    float2 acc = make_float2(0.f, 0.f);
    const unsigned* bucket = g_bucket + (size_t)b * CAP;

    for (int base = part * 32; base < n; base += 64) {
        int idx = base + lane;
        unsigned pk = (idx < n) ? __ldg(bucket + idx) : 0u;
        #pragma unroll
        for (int s = 0; s < 32; s += 2) {
            unsigned pv = __shfl_sync(0xffffffffu, pk, s + half);
            unsigned p  = pv >> 16;
            float w = __half2float(__ushort_as_half((unsigned short)(pv & 0xffffu)));
            __half2 h = __ldg(reinterpret_cast<const __half2*>(
                                  g_xTh + (size_t)p * BC) + sub);
            float2 f = __half22float2(h);
            acc.x += f.x * w;
            acc.y += f.y * w;
        }
    }

    // fold the two half-warps, then one RED.v2 per map pair per warp
    acc.x += __shfl_xor_sync(0xffffffffu, acc.x, 16);
    acc.y += __shfl_xor_sync(0xffffffffu, acc.y, 16);

    if (half == 0) {
        float* dst = g_acc + (size_t)b * BC + sub * 2;
        asm volatile("red.global.add.v2.f32 [%0], {%1, %2};"
                     :: "l"(dst), "f"(acc.x), "f"(acc.y) : "memory");
    }
}

// ---------------------------------------------------------------------------
// Finalize: g_acc [HT_BINS, BC] bin-major -> out [BC, HT_BINS] map-major, /NORM
// Tiled transpose, both sides coalesced.
// ---------------------------------------------------------------------------
__global__ void finalize_kernel(float* __restrict__ out) {
    __shared__ float tile[64][32 + 1];
    int b0 = blockIdx.x * 64;
    int t  = threadIdx.x;
    #pragma unroll
    for (int i = 0; i < 8; i++) {
        int idx = t + i * 256;          // idx = bl*32 + m
        int bl = idx >> 5;
        int m  = idx & 31;
        int b  = b0 + bl;
        if (b < HT_BINS)
            tile[bl][m] = g_acc[(size_t)b * BC + m];
    }
    __syncthreads();
    #pragma unroll
    for (int i = 0; i < 8; i++) {
        int idx = t + i * 256;          // idx = m*64 + bl
        int m  = idx >> 6;
        int bl = idx & 63;
        int b  = b0 + bl;
        if (b < HT_BINS)
            out[(size_t)m * HT_BINS + b] = tile[bl][m] * INV_NORM;
    }
}

// ---------------------------------------------------------------------------
// Launch pipeline (all async, graph-capturable)
// ---------------------------------------------------------------------------
extern "C" void kernel_launch(void* const* d_in, const int* in_sizes, int n_in,
                              void* d_out, int out_size) {
    const float* x  = (const float*)d_in[0];   // [2,16,128,128] fp32
    const int*   vp = (const int*)  d_in[1];   // vote_pixel  [4M]
    const int*   vb = (const int*)  d_in[2];   // vote_bin    [4M]
    const float* vw = (const float*)d_in[3];   // vote_weight [4M]
    float* out = (float*)d_out;                // [2,16,184,180] fp32

    const int TB = 256;

    zero_kernel       <<<((HT_BINS * BC / 4) + TB - 1) / TB, TB>>>();
    transpose_x_kernel<<<IM_PIX / 64, TB>>>(x);
    scatter_kernel    <<<(N_VOTES + TB - 1) / TB, TB>>>(x, vp, vb, vw);

    int warps = HT_BINS * 2;                   // 66240, divides evenly by 8
    accum_kernel<<<warps * 32 / TB, TB>>>();

    finalize_kernel<<<(HT_BINS + 63) / 64, TB>>>(out);
}

// round 7
// speedup vs baseline: 1.4009x; 1.0604x over previous
#include <cuda_runtime.h>
#include <cuda_fp16.h>
#include <cstdint>

// Problem constants
#define IM_PIX   16384      // 128*128 pixels
#define BC       32         // 2*16 maps
#define HT_BINS  33120      // 184*180
#define N_VOTES  4000000
#define INV_NORM (1.0f/128.0f)
#define NREP     4          // counter replicas per bin (atomic decontention)
#define RCAP     64         // capacity per replica; Poisson(30.25), 6.1 sigma + fallback
#define CAPTOT   (NREP * RCAP)   // 256 slots per bin

// Scratch (__device__ globals; allocation-free rule)
__device__ __half   g_xTh[IM_PIX * BC];                 // pixel-major fp16 table, 1 MB
__device__ float    g_acc[HT_BINS * BC];                // overflow-fallback accumulator
__device__ int      g_cnt[HT_BINS * NREP];              // replicated per-bin counters
__device__ unsigned g_bucket[(size_t)HT_BINS * CAPTOT]; // packed votes p<<16|fp16(w), 33.9 MB

// ---------------------------------------------------------------------------
// Zero counters + overflow accumulator
// ---------------------------------------------------------------------------
__global__ void zero_kernel() {
    int i = blockIdx.x * blockDim.x + threadIdx.x;
    if (i < (HT_BINS * BC) / 4)
        reinterpret_cast<float4*>(g_acc)[i] = make_float4(0.f, 0.f, 0.f, 0.f);
    if (i < (HT_BINS * NREP) / 4)
        reinterpret_cast<int4*>(g_cnt)[i] = make_int4(0, 0, 0, 0);
}

// ---------------------------------------------------------------------------
// Transpose x [BC, IM_PIX] fp32 -> g_xTh [IM_PIX, BC] fp16, tiled via smem
// ---------------------------------------------------------------------------
__global__ void transpose_x_kernel(const float* __restrict__ x) {
    __shared__ float tile[32][64 + 1];
    int p0 = blockIdx.x * 64;
    int t  = threadIdx.x;
    #pragma unroll
    for (int i = 0; i < 8; i++) {
        int idx = t + i * 256;          // idx = m*64 + pl
        int m  = idx >> 6;
        int pl = idx & 63;
        tile[m][pl] = x[(size_t)m * IM_PIX + p0 + pl];
    }
    __syncthreads();
    #pragma unroll
    for (int i = 0; i < 8; i++) {
        int idx = t + i * 256;          // idx = pl*32 + m
        int pl = idx >> 5;
        int m  = idx & 31;
        g_xTh[(size_t)(p0 + pl) * BC + m] = __float2half(tile[m][pl]);
    }
}

// ---------------------------------------------------------------------------
// Scatter: 4 votes per thread (vectorized loads). Vote j goes to replica j
// of its bin: counter g_cnt[b*4+j], slots [b*CAPTOT + j*RCAP ...).
// Overflow fallback (prob ~1e-4 chip-wide): exact atomics from original x.
// ---------------------------------------------------------------------------
__global__ void scatter_kernel(const float* __restrict__ x,
                               const int*   __restrict__ vp,
                               const int*   __restrict__ vb,
                               const float* __restrict__ vw) {
    int t = blockIdx.x * blockDim.x + threadIdx.x;
    if (t >= N_VOTES / 4) return;

    int4   p4 = reinterpret_cast<const int4*>(vp)[t];
    int4   b4 = reinterpret_cast<const int4*>(vb)[t];
    float4 w4 = reinterpret_cast<const float4*>(vw)[t];

    int    ps[4] = {p4.x, p4.y, p4.z, p4.w};
    int    bs[4] = {b4.x, b4.y, b4.z, b4.w};
    float  ws[4] = {w4.x, w4.y, w4.z, w4.w};

    #pragma unroll
    for (int j = 0; j < 4; j++) {
        int   p = ps[j];
        int   b = bs[j];
        float w = ws[j];
        int pos = atomicAdd(&g_cnt[b * NREP + j], 1);
        if (pos < RCAP) {
            unsigned packed = ((unsigned)p << 16)
                            | (unsigned)__half_as_ushort(__float2half(w));
            g_bucket[(size_t)b * CAPTOT + j * RCAP + pos] = packed;
        } else {
            float* dst = g_acc + (size_t)b * BC;
            #pragma unroll
            for (int m = 0; m < BC; m++)
                atomicAdd(dst + m, x[(size_t)m * IM_PIX + p] * w);
        }
    }
}

// ---------------------------------------------------------------------------
// Accumulate: ONE warp per bin, zero atomics, writes out directly.
//   quad = lane>>3 : which of 4 votes per step
//   sub  = lane&7  : map quad [4*sub, 4*sub+4)  -> one LDG.64 (4 halves)
// Pads are packed=0 -> w=+0.0 -> harmless FMA.
// Final: fold quads with 2 shfl_xor rounds; lanes 0-7 store 4 maps each.
// ---------------------------------------------------------------------------
__global__ void accum_kernel(float* __restrict__ out) {
    int b = (blockIdx.x * blockDim.x + threadIdx.x) >> 5;
    if (b >= HT_BINS) return;
    int lane = threadIdx.x & 31;
    int quad = lane >> 3;
    int sub  = lane & 7;

    float4 acc = make_float4(0.f, 0.f, 0.f, 0.f);
    if (quad == 0)   // fold (normally zero) overflow accumulator once
        acc = *reinterpret_cast<const float4*>(g_acc + (size_t)b * BC + sub * 4);

    const uint4 c4 = *reinterpret_cast<const uint4*>(g_cnt + b * NREP);
    const unsigned cnts[4] = {c4.x, c4.y, c4.z, c4.w};
    const unsigned* bucket = g_bucket + (size_t)b * CAPTOT;
    const char* xbase = reinterpret_cast<const char*>(g_xTh);

    #pragma unroll
    for (int r = 0; r < NREP; r++) {
        int n = (int)cnts[r];
        if (n > RCAP) n = RCAP;
        const unsigned* seg = bucket + r * RCAP;
        for (int base = 0; base < n; base += 32) {
            int idx = base + lane;
            unsigned pk = (idx < n) ? __ldg(seg + idx) : 0u;
            #pragma unroll
            for (int s = 0; s < 32; s += 4) {
                if (base + s >= n) break;                 // warp-uniform
                unsigned pv = __shfl_sync(0xffffffffu, pk, s + quad);
                float w = __half2float(__ushort_as_half((unsigned short)(pv & 0xffffu)));
                unsigned off = (pv >> 10) & 0xFFFFC0u;    // pixel * 64 bytes
                uint2 u = __ldg(reinterpret_cast<const uint2*>(xbase + off + sub * 8));
                float2 f0 = __half22float2(*reinterpret_cast<__half2*>(&u.x));
                float2 f1 = __half22float2(*reinterpret_cast<__half2*>(&u.y));
                acc.x += f0.x * w;
                acc.y += f0.y * w;
                acc.z += f1.x * w;
                acc.w += f1.y * w;
            }
        }
    }

    // fold the 4 quads
    #pragma unroll
    for (int ofs = 8; ofs <= 16; ofs <<= 1) {
        acc.x += __shfl_xor_sync(0xffffffffu, acc.x, ofs);
        acc.y += __shfl_xor_sync(0xffffffffu, acc.y, ofs);
        acc.z += __shfl_xor_sync(0xffffffffu, acc.z, ofs);
        acc.w += __shfl_xor_sync(0xffffffffu, acc.w, ofs);
    }

    if (quad == 0) {
        int m0 = sub * 4;
        out[(size_t)(m0 + 0) * HT_BINS + b] = acc.x * INV_NORM;
        out[(size_t)(m0 + 1) * HT_BINS + b] = acc.y * INV_NORM;
        out[(size_t)(m0 + 2) * HT_BINS + b] = acc.z * INV_NORM;
        out[(size_t)(m0 + 3) * HT_BINS + b] = acc.w * INV_NORM;
    }
}

// ---------------------------------------------------------------------------
// Launch pipeline (all async, graph-capturable)
// ---------------------------------------------------------------------------
extern "C" void kernel_launch(void* const* d_in, const int* in_sizes, int n_in,
                              void* d_out, int out_size) {
    const float* x  = (const float*)d_in[0];   // [2,16,128,128] fp32
    const int*   vp = (const int*)  d_in[1];   // vote_pixel  [4M]
    const int*   vb = (const int*)  d_in[2];   // vote_bin    [4M]
    const float* vw = (const float*)d_in[3];   // vote_weight [4M]
    float* out = (float*)d_out;                // [2,16,184,180] fp32

    const int TB = 256;

    zero_kernel       <<<((HT_BINS * BC / 4) + TB - 1) / TB, TB>>>();
    transpose_x_kernel<<<IM_PIX / 64, TB>>>(x);
    scatter_kernel    <<<((N_VOTES / 4) + TB - 1) / TB, TB>>>(x, vp, vb, vw);
    accum_kernel      <<<(HT_BINS * 32 + TB - 1) / TB, TB>>>(out);
}

// round 8
// speedup vs baseline: 1.4642x; 1.0452x over previous
#include <cuda_runtime.h>
#include <cuda_fp16.h>
#include <cstdint>

// Problem constants
#define IM_PIX   16384      // 128*128 pixels
#define BC       32         // 2*16 maps
#define HT_BINS  33120      // 184*180
#define N_VOTES  4000000
#define INV_NORM (1.0f/128.0f)
#define NREP     4          // bucket segments per bin
#define RCAP     64         // capacity per segment; Poisson(30.25) + exact fallback
#define CAPTOT   (NREP * RCAP)

// Scratch (__device__ globals; allocation-free rule)
__device__ __half   g_xTh[IM_PIX * BC];                 // pixel-major fp16 table, 1 MB
__device__ float    g_acc[HT_BINS * BC];                // overflow-fallback accumulator
__device__ int      g_cnt[HT_BINS * NREP];              // per-segment counters
__device__ unsigned g_bucket[(size_t)HT_BINS * CAPTOT]; // packed votes p<<16|fp16(w)

// ---------------------------------------------------------------------------
// Fused init: blocks [0,256) transpose x -> fp16 pixel-major; the rest zero
// the accumulator and counters.
// ---------------------------------------------------------------------------
#define TRANS_BLOCKS (IM_PIX / 64)          // 256
#define ZERO_N       ((HT_BINS * BC + HT_BINS * NREP) / 4)
#define ZERO_BLOCKS  ((ZERO_N + 255) / 256)

__global__ void init_kernel(const float* __restrict__ x) {
    if (blockIdx.x < TRANS_BLOCKS) {
        __shared__ float tile[32][64 + 1];
        int p0 = blockIdx.x * 64;
        int t  = threadIdx.x;
        #pragma unroll
        for (int i = 0; i < 8; i++) {
            int idx = t + i * 256;          // idx = m*64 + pl
            int m  = idx >> 6;
            int pl = idx & 63;
            tile[m][pl] = x[(size_t)m * IM_PIX + p0 + pl];
        }
        __syncthreads();
        #pragma unroll
        for (int i = 0; i < 8; i++) {
            int idx = t + i * 256;          // idx = pl*32 + m
            int pl = idx >> 5;
            int m  = idx & 31;
            g_xTh[(size_t)(p0 + pl) * BC + m] = __float2half(tile[m][pl]);
        }
    } else {
        int i = (blockIdx.x - TRANS_BLOCKS) * blockDim.x + threadIdx.x;
        if (i < (HT_BINS * BC) / 4)
            reinterpret_cast<float4*>(g_acc)[i] = make_float4(0.f, 0.f, 0.f, 0.f);
        int j = i - (HT_BINS * BC) / 4;
        if (j >= 0 && j < (HT_BINS * NREP) / 4)
            reinterpret_cast<int4*>(g_cnt)[j] = make_int4(0, 0, 0, 0);
    }
}

// ---------------------------------------------------------------------------
// Scatter: 8 votes per thread -> 8 independent returning atomics in flight
// (MLP against the ~320cyc L2 atomic latency). Vote k uses segment k&3.
// Overflow fallback (prob ~0): exact atomics from original x.
// ---------------------------------------------------------------------------
__global__ void scatter_kernel(const float* __restrict__ x,
                               const int*   __restrict__ vp,
                               const int*   __restrict__ vb,
                               const float* __restrict__ vw) {
    int t = blockIdx.x * blockDim.x + threadIdx.x;
    if (t >= N_VOTES / 8) return;

    int4   pa = reinterpret_cast<const int4*>(vp)[2 * t];
    int4   pb = reinterpret_cast<const int4*>(vp)[2 * t + 1];
    int4   ba = reinterpret_cast<const int4*>(vb)[2 * t];
    int4   bb = reinterpret_cast<const int4*>(vb)[2 * t + 1];
    float4 wa = reinterpret_cast<const float4*>(vw)[2 * t];
    float4 wb = reinterpret_cast<const float4*>(vw)[2 * t + 1];

    int   ps[8] = {pa.x, pa.y, pa.z, pa.w, pb.x, pb.y, pb.z, pb.w};
    int   bs[8] = {ba.x, ba.y, ba.z, ba.w, bb.x, bb.y, bb.z, bb.w};
    float ws[8] = {wa.x, wa.y, wa.z, wa.w, wb.x, wb.y, wb.z, wb.w};

    int pos[8];
    #pragma unroll
    for (int k = 0; k < 8; k++)
        pos[k] = atomicAdd(&g_cnt[bs[k] * NREP + (k & 3)], 1);

    #pragma unroll
    for (int k = 0; k < 8; k++) {
        if (pos[k] < RCAP) {
            unsigned packed = ((unsigned)ps[k] << 16)
                            | (unsigned)__half_as_ushort(__float2half(ws[k]));
            g_bucket[(size_t)bs[k] * CAPTOT + (k & 3) * RCAP + pos[k]] = packed;
        } else {
            float* dst = g_acc + (size_t)bs[k] * BC;
            #pragma unroll
            for (int m = 0; m < BC; m++)
                atomicAdd(dst + m, x[(size_t)m * IM_PIX + ps[k]] * ws[k]);
        }
    }
}

// ---------------------------------------------------------------------------
// Accumulate: block = 8 warps = 4 bins x 2 warps. Warp part p takes segments
// {2p, 2p+1}. Lane = (quad, sub): 4 votes per step, 4 maps per lane (LDG.64).
// Partials combined through smem; block writes 4 bins' outputs coalesced.
// ---------------------------------------------------------------------------
__global__ void accum_kernel(float* __restrict__ out) {
    __shared__ float s_part[4][2][32];     // [bin_local][part][map]

    int wid  = threadIdx.x >> 5;
    int lane = threadIdx.x & 31;
    int bl   = wid >> 1;                   // bin within block
    int part = wid & 1;
    int b0   = blockIdx.x * 4;
    int b    = b0 + bl;                    // HT_BINS % 4 == 0
    int quad = lane >> 3;
    int sub  = lane & 7;

    float4 acc = make_float4(0.f, 0.f, 0.f, 0.f);
    if (part == 0 && quad == 0)            // fold (normally zero) overflow row once
        acc = *reinterpret_cast<const float4*>(g_acc + (size_t)b * BC + sub * 4);

    const unsigned* bucket = g_bucket + (size_t)b * CAPTOT;
    const char* xbase = reinterpret_cast<const char*>(g_xTh);

    #pragma unroll
    for (int rr = 0; rr < 2; rr++) {
        int r = part * 2 + rr;
        int n = g_cnt[b * NREP + r];
        if (n > RCAP) n = RCAP;
        const unsigned* seg = bucket + r * RCAP;
        #pragma unroll
        for (int base = 0; base < RCAP; base += 32) {
            if (base >= n) break;          // warp-uniform
            int idx = base + lane;
            unsigned pk = (idx < n) ? __ldg(seg + idx) : 0u;
            #pragma unroll
            for (int s = 0; s < 32; s += 4) {
                if (base + s >= n) break;  // warp-uniform
                unsigned pv = __shfl_sync(0xffffffffu, pk, s + quad);
                float w = __half2float(__ushort_as_half((unsigned short)(pv & 0xffffu)));
                unsigned off = (pv >> 10) & 0xFFFFC0u;   // pixel * 64 bytes
                uint2 u = __ldg(reinterpret_cast<const uint2*>(xbase + off + sub * 8));
                float2 f0 = __half22float2(*reinterpret_cast<__half2*>(&u.x));
                float2 f1 = __half22float2(*reinterpret_cast<__half2*>(&u.y));
                acc.x += f0.x * w;
                acc.y += f0.y * w;
                acc.z += f1.x * w;
                acc.w += f1.y * w;
            }
        }
    }

    // fold the 4 quads inside each warp
    #pragma unroll
    for (int ofs = 8; ofs <= 16; ofs <<= 1) {
        acc.x += __shfl_xor_sync(0xffffffffu, acc.x, ofs);
        acc.y += __shfl_xor_sync(0xffffffffu, acc.y, ofs);
        acc.z += __shfl_xor_sync(0xffffffffu, acc.z, ofs);
        acc.w += __shfl_xor_sync(0xffffffffu, acc.w, ofs);
    }

    if (quad == 0) {
        int m0 = sub * 4;
        s_part[bl][part][m0 + 0] = acc.x;
        s_part[bl][part][m0 + 1] = acc.y;
        s_part[bl][part][m0 + 2] = acc.z;
        s_part[bl][part][m0 + 3] = acc.w;
    }
    __syncthreads();

    // 128 output threads: t = m*4 + bl  -> 4 consecutive bins per map (16B coalesced)
    int t = threadIdx.x;
    if (t < 128) {
        int m   = t >> 2;
        int obl = t & 3;
        float v = s_part[obl][0][m] + s_part[obl][1][m];
        out[(size_t)m * HT_BINS + b0 + obl] = v * INV_NORM;
    }
}

// ---------------------------------------------------------------------------
// Launch pipeline (all async, graph-capturable)
// ---------------------------------------------------------------------------
extern "C" void kernel_launch(void* const* d_in, const int* in_sizes, int n_in,
                              void* d_out, int out_size) {
    const float* x  = (const float*)d_in[0];   // [2,16,128,128] fp32
    const int*   vp = (const int*)  d_in[1];   // vote_pixel  [4M]
    const int*   vb = (const int*)  d_in[2];   // vote_bin    [4M]
    const float* vw = (const float*)d_in[3];   // vote_weight [4M]
    float* out = (float*)d_out;                // [2,16,184,180] fp32

    const int TB = 256;

    init_kernel   <<<TRANS_BLOCKS + ZERO_BLOCKS, TB>>>(x);
    scatter_kernel<<<((N_VOTES / 8) + TB - 1) / TB, TB>>>(x, vp, vb, vw);
    accum_kernel  <<<HT_BINS / 4, TB>>>(out);
}

// round 9
// speedup vs baseline: 1.4676x; 1.0023x over previous
#include <cuda_runtime.h>
#include <cuda_fp16.h>
#include <cstdint>

// Problem constants
#define IM_PIX   16384      // 128*128 pixels
#define BC       32         // 2*16 maps
#define HT_BINS  33120      // 184*180
#define N_VOTES  4000000
#define INV_NORM (1.0f/128.0f)
#define NREP     4          // bucket segments per bin
#define RCAP     64         // capacity per segment; Poisson(30.25) + exact fallback
#define CAPTOT   (NREP * RCAP)

// Scratch (__device__ globals; allocation-free rule)
__device__ __half   g_xTh[IM_PIX * BC];                 // pixel-major fp16 table, 1 MB
__device__ float    g_acc[HT_BINS * BC];                // overflow-fallback accumulator
__device__ int      g_cnt[HT_BINS * NREP];              // per-segment counters
__device__ unsigned g_bucket[(size_t)HT_BINS * CAPTOT]; // packed votes p<<16|fp16(w)

// ---------------------------------------------------------------------------
// Fused init: blocks [0,256) transpose x -> fp16 pixel-major; the rest zero
// the accumulator and counters.
// ---------------------------------------------------------------------------
#define TRANS_BLOCKS (IM_PIX / 64)          // 256
#define ZERO_N       ((HT_BINS * BC + HT_BINS * NREP) / 4)
#define ZERO_BLOCKS  ((ZERO_N + 255) / 256)

__global__ void init_kernel(const float* __restrict__ x) {
    if (blockIdx.x < TRANS_BLOCKS) {
        __shared__ float tile[32][64 + 1];
        int p0 = blockIdx.x * 64;
        int t  = threadIdx.x;
        #pragma unroll
        for (int i = 0; i < 8; i++) {
            int idx = t + i * 256;          // idx = m*64 + pl
            int m  = idx >> 6;
            int pl = idx & 63;
            tile[m][pl] = x[(size_t)m * IM_PIX + p0 + pl];
        }
        __syncthreads();
        #pragma unroll
        for (int i = 0; i < 8; i++) {
            int idx = t + i * 256;          // idx = pl*32 + m
            int pl = idx >> 5;
            int m  = idx & 31;
            g_xTh[(size_t)(p0 + pl) * BC + m] = __float2half(tile[m][pl]);
        }
    } else {
        int i = (blockIdx.x - TRANS_BLOCKS) * blockDim.x + threadIdx.x;
        if (i < (HT_BINS * BC) / 4)
            reinterpret_cast<float4*>(g_acc)[i] = make_float4(0.f, 0.f, 0.f, 0.f);
        int j = i - (HT_BINS * BC) / 4;
        if (j >= 0 && j < (HT_BINS * NREP) / 4)
            reinterpret_cast<int4*>(g_cnt)[j] = make_int4(0, 0, 0, 0);
    }
}

// ---------------------------------------------------------------------------
// Scatter: 8 votes per thread. LSU-floor bound (~2 ops/vote); streaming
// hints keep L1 clean. Vote k uses segment k&3 of its bin.
// Overflow fallback (prob ~0): exact atomics from original x.
// ---------------------------------------------------------------------------
__global__ void scatter_kernel(const float* __restrict__ x,
                               const int*   __restrict__ vp,
                               const int*   __restrict__ vb,
                               const float* __restrict__ vw) {
    int t = blockIdx.x * blockDim.x + threadIdx.x;
    if (t >= N_VOTES / 8) return;

    int4   pa = __ldcs(reinterpret_cast<const int4*>(vp) + 2 * t);
    int4   pb = __ldcs(reinterpret_cast<const int4*>(vp) + 2 * t + 1);
    int4   ba = __ldcs(reinterpret_cast<const int4*>(vb) + 2 * t);
    int4   bb = __ldcs(reinterpret_cast<const int4*>(vb) + 2 * t + 1);
    float4 wa = __ldcs(reinterpret_cast<const float4*>(vw) + 2 * t);
    float4 wb = __ldcs(reinterpret_cast<const float4*>(vw) + 2 * t + 1);

    int   ps[8] = {pa.x, pa.y, pa.z, pa.w, pb.x, pb.y, pb.z, pb.w};
    int   bs[8] = {ba.x, ba.y, ba.z, ba.w, bb.x, bb.y, bb.z, bb.w};
    float ws[8] = {wa.x, wa.y, wa.z, wa.w, wb.x, wb.y, wb.z, wb.w};

    int pos[8];
    #pragma unroll
    for (int k = 0; k < 8; k++)
        pos[k] = atomicAdd(&g_cnt[bs[k] * NREP + (k & 3)], 1);

    #pragma unroll
    for (int k = 0; k < 8; k++) {
        if (pos[k] < RCAP) {
            unsigned packed = ((unsigned)ps[k] << 16)
                            | (unsigned)__half_as_ushort(__float2half(ws[k]));
            __stcs(&g_bucket[(size_t)bs[k] * CAPTOT + (k & 3) * RCAP + pos[k]], packed);
        } else {
            float* dst = g_acc + (size_t)bs[k] * BC;
            #pragma unroll
            for (int m = 0; m < BC; m++)
                atomicAdd(dst + m, x[(size_t)m * IM_PIX + ps[k]] * ws[k]);
        }
    }
}

// ---------------------------------------------------------------------------
// Accumulate: block = 8 warps = 4 bins x 2 warps; warp part p takes segments
// {2p, 2p+1}.
//   oct = lane>>2 : which of 8 votes per step
//   sub = lane&3  : map octet [8*sub, 8*sub+8) -> one LDG.128 (8 halves)
// Pads (idx >= n) have pk=0 -> w=+0.0 -> harmless FMAs; no inner branch.
// Partials fold: shfl_xor over oct (4,8,16), then smem combine across parts.
// Block writes 4 bins' outputs coalesced.
// ---------------------------------------------------------------------------
__global__ void accum_kernel(float* __restrict__ out) {
    __shared__ float s_part[4][2][32];     // [bin_local][part][map]

    int wid  = threadIdx.x >> 5;
    int lane = threadIdx.x & 31;
    int bl   = wid >> 1;
    int part = wid & 1;
    int b0   = blockIdx.x * 4;
    int b    = b0 + bl;                    // HT_BINS % 4 == 0
    int oct  = lane >> 2;
    int sub  = lane & 3;

    float acc[8] = {0.f, 0.f, 0.f, 0.f, 0.f, 0.f, 0.f, 0.f};
    if (part == 0 && oct == 0) {           // fold (normally zero) overflow row once
        float4 a0 = *reinterpret_cast<const float4*>(g_acc + (size_t)b * BC + sub * 8);
        float4 a1 = *reinterpret_cast<const float4*>(g_acc + (size_t)b * BC + sub * 8 + 4);
        acc[0] = a0.x; acc[1] = a0.y; acc[2] = a0.z; acc[3] = a0.w;
        acc[4] = a1.x; acc[5] = a1.y; acc[6] = a1.z; acc[7] = a1.w;
    }

    const unsigned* bucket = g_bucket + (size_t)b * CAPTOT;
    const char* xbase = reinterpret_cast<const char*>(g_xTh);

    #pragma unroll
    for (int rr = 0; rr < 2; rr++) {
        int r = part * 2 + rr;
        int n = g_cnt[b * NREP + r];
        if (n > RCAP) n = RCAP;
        const unsigned* seg = bucket + r * RCAP;
        #pragma unroll
        for (int base = 0; base < RCAP; base += 32) {
            if (base >= n) break;          // warp-uniform, chunk granularity only
            int idx = base + lane;
            unsigned pk = (idx < n) ? __ldg(seg + idx) : 0u;
            #pragma unroll
            for (int s = 0; s < 32; s += 8) {
                unsigned pv = __shfl_sync(0xffffffffu, pk, s + oct);
                float w = __half2float(__ushort_as_half((unsigned short)(pv & 0xffffu)));
                unsigned off = (pv >> 10) & 0xFFFFC0u;   // pixel * 64 bytes
                uint4 u = __ldg(reinterpret_cast<const uint4*>(xbase + off + sub * 16));
                float2 f0 = __half22float2(*reinterpret_cast<__half2*>(&u.x));
                float2 f1 = __half22float2(*reinterpret_cast<__half2*>(&u.y));
                float2 f2 = __half22float2(*reinterpret_cast<__half2*>(&u.z));
                float2 f3 = __half22float2(*reinterpret_cast<__half2*>(&u.w));
                acc[0] += f0.x * w;  acc[1] += f0.y * w;
                acc[2] += f1.x * w;  acc[3] += f1.y * w;
                acc[4] += f2.x * w;  acc[5] += f2.y * w;
                acc[6] += f3.x * w;  acc[7] += f3.y * w;
            }
        }
    }

    // fold the 8 oct groups (vote selectors): xor offsets 4, 8, 16
    #pragma unroll
    for (int ofs = 4; ofs <= 16; ofs <<= 1) {
        #pragma unroll
        for (int i = 0; i < 8; i++)
            acc[i] += __shfl_xor_sync(0xffffffffu, acc[i], ofs);
    }

    if (oct == 0) {                        // lanes 0..3 hold maps [8*sub, 8*sub+8)
        #pragma unroll
        for (int i = 0; i < 8; i++)
            s_part[bl][part][sub * 8 + i] = acc[i];
    }
    __syncthreads();

    // 128 output threads: t = m*4 + bl -> 4 consecutive bins per map (16B coalesced)
    int t = threadIdx.x;
    if (t < 128) {
        int m   = t >> 2;
        int obl = t & 3;
        float v = s_part[obl][0][m] + s_part[obl][1][m];
        out[(size_t)m * HT_BINS + b0 + obl] = v * INV_NORM;
    }
}

// ---------------------------------------------------------------------------
// Launch pipeline (all async, graph-capturable)
// ---------------------------------------------------------------------------
extern "C" void kernel_launch(void* const* d_in, const int* in_sizes, int n_in,
                              void* d_out, int out_size) {
    const float* x  = (const float*)d_in[0];   // [2,16,128,128] fp32
    const int*   vp = (const int*)  d_in[1];   // vote_pixel  [4M]
    const int*   vb = (const int*)  d_in[2];   // vote_bin    [4M]
    const float* vw = (const float*)d_in[3];   // vote_weight [4M]
    float* out = (float*)d_out;                // [2,16,184,180] fp32

    const int TB = 256;

    init_kernel   <<<TRANS_BLOCKS + ZERO_BLOCKS, TB>>>(x);
    scatter_kernel<<<((N_VOTES / 8) + TB - 1) / TB, TB>>>(x, vp, vb, vw);
    accum_kernel  <<<HT_BINS / 4, TB>>>(out);
}

// round 10
// speedup vs baseline: 1.6720x; 1.1393x over previous
#include <cuda_runtime.h>
#include <cuda_fp16.h>
#include <cstdint>

// Problem constants
#define IM_PIX   16384      // 128*128 pixels
#define BC       32         // 2*16 maps
#define HT_BINS  33120      // 184*180
#define N_VOTES  4000000
#define INV_NORM (1.0f/128.0f)
#define NREP     8          // bucket segments per bin
#define RCAP     32         // capacity per segment; Pois(15.1), P(>32)~3e-5 + exact fallback
#define CAPTOT   (NREP * RCAP)   // 256

// Scratch (__device__ globals; allocation-free rule). Zero-initialized at load;
// accum_kernel re-zeroes g_cnt/g_acc at the end of every call (deterministic).
__device__ __half   g_xTh[IM_PIX * BC];                 // pixel-major fp16 table, 1 MB
__device__ float    g_acc[HT_BINS * BC];                // overflow-fallback accumulator
__device__ int      g_cnt[HT_BINS * NREP];              // per-segment counters
__device__ unsigned g_bucket[(size_t)HT_BINS * CAPTOT]; // packed votes p<<16|fp16(w)

#define TRANS_BLOCKS 256                   // IM_PIX/64 transpose tiles
#define SCAT_THREADS (N_VOTES / 8)         // 500,000
#define SCAT_BLOCKS  ((SCAT_THREADS + 255) / 256)

// ---------------------------------------------------------------------------
// Fused kernel: blocks [0,256) transpose x -> g_xTh (fp16 pixel-major);
// blocks [256, ...) scatter 8 votes/thread into per-bin segment buckets.
// Transpose blocks launch first and hide under the scatter work.
// ---------------------------------------------------------------------------
__global__ void scatter_transpose_kernel(const float* __restrict__ x,
                                         const int*   __restrict__ vp,
                                         const int*   __restrict__ vb,
                                         const float* __restrict__ vw) {
    if (blockIdx.x < TRANS_BLOCKS) {
        __shared__ float tile[32][64 + 1];
        int p0 = blockIdx.x * 64;
        int t  = threadIdx.x;
        #pragma unroll
        for (int i = 0; i < 8; i++) {
            int idx = t + i * 256;          // idx = m*64 + pl
            int m  = idx >> 6;
            int pl = idx & 63;
            tile[m][pl] = x[(size_t)m * IM_PIX + p0 + pl];
        }
        __syncthreads();
        #pragma unroll
        for (int i = 0; i < 8; i++) {
            int idx = t + i * 256;          // idx = pl*32 + m
            int pl = idx >> 5;
            int m  = idx & 31;
            g_xTh[(size_t)(p0 + pl) * BC + m] = __float2half(tile[m][pl]);
        }
        return;
    }

    int t = (blockIdx.x - TRANS_BLOCKS) * blockDim.x + threadIdx.x;
    if (t >= SCAT_THREADS) return;

    int4   pa = __ldcs(reinterpret_cast<const int4*>(vp) + 2 * t);
    int4   pb = __ldcs(reinterpret_cast<const int4*>(vp) + 2 * t + 1);
    int4   ba = __ldcs(reinterpret_cast<const int4*>(vb) + 2 * t);
    int4   bb = __ldcs(reinterpret_cast<const int4*>(vb) + 2 * t + 1);
    float4 wa = __ldcs(reinterpret_cast<const float4*>(vw) + 2 * t);
    float4 wb = __ldcs(reinterpret_cast<const float4*>(vw) + 2 * t + 1);

    int   ps[8] = {pa.x, pa.y, pa.z, pa.w, pb.x, pb.y, pb.z, pb.w};
    int   bs[8] = {ba.x, ba.y, ba.z, ba.w, bb.x, bb.y, bb.z, bb.w};
    float ws[8] = {wa.x, wa.y, wa.z, wa.w, wb.x, wb.y, wb.z, wb.w};

    int pos[8];
    #pragma unroll
    for (int k = 0; k < 8; k++)                 // vote k -> segment k of its bin
        pos[k] = atomicAdd(&g_cnt[bs[k] * NREP + k], 1);

    #pragma unroll
    for (int k = 0; k < 8; k++) {
        if (pos[k] < RCAP) {
            unsigned packed = ((unsigned)ps[k] << 16)
                            | (unsigned)__half_as_ushort(__float2half(ws[k]));
            __stcs(&g_bucket[(size_t)bs[k] * CAPTOT + k * RCAP + pos[k]], packed);
        } else {                                 // ~1e-5 of votes: exact fallback
            float* dst = g_acc + (size_t)bs[k] * BC;
            #pragma unroll
            for (int m = 0; m < BC; m++)
                atomicAdd(dst + m, x[(size_t)m * IM_PIX + ps[k]] * ws[k]);
        }
    }
}

// ---------------------------------------------------------------------------
// Accumulate: block = 8 warps = 4 bins x 2 warps; warp part p owns segments
// [4p, 4p+4). Each segment is exactly one 32-wide chunk:
//   - 1 uint4 LDG for the 4 counters
//   - 4 independent bucket LDGs issued up front (MLP vs L2 latency)
//   oct = lane>>2 : which of 8 votes per step;  sub = lane&3 : map octet
//   -> one LDG.128 (8 halves) per lane per step
// Pads (lane >= n) have pk=0 -> w=+0.0 -> harmless FMAs.
// Tail: fold, smem combine, coalesced output, then RE-ZERO g_cnt/g_acc for
// the next call.
// ---------------------------------------------------------------------------
__global__ void accum_kernel(float* __restrict__ out) {
    __shared__ float s_part[4][2][32];     // [bin_local][part][map]

    int wid  = threadIdx.x >> 5;
    int lane = threadIdx.x & 31;
    int bl   = wid >> 1;
    int part = wid & 1;
    int b0   = blockIdx.x * 4;
    int b    = b0 + bl;                    // HT_BINS % 4 == 0
    int oct  = lane >> 2;
    int sub  = lane & 3;

    // counters for my 4 segments: one 16B load
    uint4 c4 = *reinterpret_cast<const uint4*>(g_cnt + b * NREP + part * 4);
    int n[4] = {(int)c4.x, (int)c4.y, (int)c4.z, (int)c4.w};
    #pragma unroll
    for (int rr = 0; rr < 4; rr++) if (n[rr] > RCAP) n[rr] = RCAP;

    // all 4 bucket chunks in flight before any processing
    const unsigned* segbase = g_bucket + (size_t)b * CAPTOT + part * (4 * RCAP);
    unsigned pk[4];
    #pragma unroll
    for (int rr = 0; rr < 4; rr++)
        pk[rr] = (lane < n[rr]) ? __ldg(segbase + rr * RCAP + lane) : 0u;

    float acc[8] = {0.f, 0.f, 0.f, 0.f, 0.f, 0.f, 0.f, 0.f};
    if (part == 0 && oct == 0) {           // fold (normally zero) overflow row once
        float4 a0 = *reinterpret_cast<const float4*>(g_acc + (size_t)b * BC + sub * 8);
        float4 a1 = *reinterpret_cast<const float4*>(g_acc + (size_t)b * BC + sub * 8 + 4);
        acc[0] = a0.x; acc[1] = a0.y; acc[2] = a0.z; acc[3] = a0.w;
        acc[4] = a1.x; acc[5] = a1.y; acc[6] = a1.z; acc[7] = a1.w;
    }

    const char* xbase = reinterpret_cast<const char*>(g_xTh);

    #pragma unroll
    for (int rr = 0; rr < 4; rr++) {
        #pragma unroll
        for (int s = 0; s < RCAP; s += 8) {
            if (s >= n[rr]) break;         // warp-uniform
            unsigned pv = __shfl_sync(0xffffffffu, pk[rr], s + oct);
            float w = __half2float(__ushort_as_half((unsigned short)(pv & 0xffffu)));
            unsigned off = (pv >> 10) & 0xFFFFC0u;   // pixel * 64 bytes
            uint4 u = __ldg(reinterpret_cast<const uint4*>(xbase + off + sub * 16));
            float2 f0 = __half22float2(*reinterpret_cast<__half2*>(&u.x));
            float2 f1 = __half22float2(*reinterpret_cast<__half2*>(&u.y));
            float2 f2 = __half22float2(*reinterpret_cast<__half2*>(&u.z));
            float2 f3 = __half22float2(*reinterpret_cast<__half2*>(&u.w));
            acc[0] += f0.x * w;  acc[1] += f0.y * w;
            acc[2] += f1.x * w;  acc[3] += f1.y * w;
            acc[4] += f2.x * w;  acc[5] += f2.y * w;
            acc[6] += f3.x * w;  acc[7] += f3.y * w;
        }
    }

    // fold the 8 oct groups (vote selectors): xor offsets 4, 8, 16
    #pragma unroll
    for (int ofs = 4; ofs <= 16; ofs <<= 1) {
        #pragma unroll
        for (int i = 0; i < 8; i++)
            acc[i] += __shfl_xor_sync(0xffffffffu, acc[i], ofs);
    }

    if (oct == 0) {                        // lanes 0..3 hold maps [8*sub, 8*sub+8)
        #pragma unroll
        for (int i = 0; i < 8; i++)
            s_part[bl][part][sub * 8 + i] = acc[i];
    }
    __syncthreads();

    int t = threadIdx.x;
    if (t < 128) {
        // t = m*4 + bl -> 4 consecutive bins per map (16B coalesced)
        int m   = t >> 2;
        int obl = t & 3;
        float v = s_part[obl][0][m] + s_part[obl][1][m];
        out[(size_t)m * HT_BINS + b0 + obl] = v * INV_NORM;
    }
    // re-zero state for the next call (all reads of g_cnt/g_acc happened
    // before the __syncthreads above)
    if (t < 8)
        reinterpret_cast<int4*>(g_cnt + b0 * NREP)[t] = make_int4(0, 0, 0, 0);
    if (t >= 128 && t < 160)
        reinterpret_cast<float4*>(g_acc + (size_t)b0 * BC)[t - 128] =
            make_float4(0.f, 0.f, 0.f, 0.f);
}

// ---------------------------------------------------------------------------
// Launch pipeline: 2 kernels, all async, graph-capturable
// ---------------------------------------------------------------------------
extern "C" void kernel_launch(void* const* d_in, const int* in_sizes, int n_in,
                              void* d_out, int out_size) {
    const float* x  = (const float*)d_in[0];   // [2,16,128,128] fp32
    const int*   vp = (const int*)  d_in[1];   // vote_pixel  [4M]
    const int*   vb = (const int*)  d_in[2];   // vote_bin    [4M]
    const float* vw = (const float*)d_in[3];   // vote_weight [4M]
    float* out = (float*)d_out;                // [2,16,184,180] fp32

    scatter_transpose_kernel<<<TRANS_BLOCKS + SCAT_BLOCKS, 256>>>(x, vp, vb, vw);
    accum_kernel            <<<HT_BINS / 4, 256>>>(out);
}